// round 11
// baseline (speedup 1.0000x reference)
#include <cuda_runtime.h>
#include <cuda_fp16.h>
#include <cstdint>

// AffineCouplingLayer via legacy tensor pipe (mma.sync fp16, sm_100-safe).
// B=524288 rows, D=64. cin = even cols (32).
//   h1 = relu(cin@W1+b1); h2 = relu(h1@W2+b2); st = h2@W3+b3
//   s = tanh(st[:32]); y = x with odd cols = x_odd*exp(s)+t
// out = [ y (B*64 f32) | s (B*32 f32) ]
//
// Single-product fp16 (rel_err ~4.5e-4 < 1e-3). Per-warp tile M=16, N=64;
// 8 warps/CTA -> 128 rows/CTA; 2 CTAs/SM. Activations register-resident.
// One ldmatrix.x4.trans feeds TWO j-chunks (lanes 0-15 -> j0, 16-31 -> j1).
// Register-direct epilogue (y AND s from regs), barrier-free tile loop.
//
// NEW: depth-1 software pipeline on LDSM — each iteration prefetches the
// NEXT weight chunk (across layer and tile boundaries: the handoff chunk
// rides through the epilogue ALU) before consuming the current one.
// Swizzle term x7 = lane15&7 is loop-invariant (row bases = 0 mod 8), so
// chunk offsets are 4 per-thread constants -> 1 IADD per ldsm address.

#define TPB          256
#define ROWS_PER_CTA 128

// ---- SMEM layout (bytes) ----
#define WH      0            // 160 rows * 128B = 20480 (fp16 weights, SW128)
#define BIAS_O  20480        // 192 f32
#define SMEM_BYTES 21248

#define SWZ(o) ((o) ^ (((o) >> 3) & 0x70))

static __device__ __forceinline__ uint32_t smem_u32_of(const void* p) {
    uint32_t a;
    asm("{ .reg .u64 t; cvta.to.shared.u64 t, %1; cvt.u32.u64 %0, t; }" : "=r"(a) : "l"(p));
    return a;
}

static __device__ __forceinline__ uint32_t pack_f16(float lo, float hi) {
    uint32_t r;
    asm("cvt.rn.f16x2.f32 %0, %1, %2;" : "=r"(r) : "f"(hi), "f"(lo));
    return r;
}

static __device__ __forceinline__ float tanh_fast(float v) {
    return 1.0f - __fdividef(2.0f, __expf(2.0f * v) + 1.0f);
}

static __device__ __forceinline__ void mma16816(float* c, const uint32_t* a,
                                                uint32_t b0, uint32_t b1) {
    asm volatile(
        "mma.sync.aligned.m16n8k16.row.col.f32.f16.f16.f32 "
        "{%0,%1,%2,%3}, {%4,%5,%6,%7}, {%8,%9}, {%0,%1,%2,%3};"
        : "+f"(c[0]), "+f"(c[1]), "+f"(c[2]), "+f"(c[3])
        : "r"(a[0]), "r"(a[1]), "r"(a[2]), "r"(a[3]), "r"(b0), "r"(b1));
}

static __device__ __forceinline__ void ldsm4t(uint32_t addr, uint32_t* b) {
    asm volatile("ldmatrix.sync.aligned.m8n8.x4.trans.shared.b16 {%0,%1,%2,%3}, [%4];"
                 : "=r"(b[0]), "=r"(b[1]), "=r"(b[2]), "=r"(b[3]) : "r"(addr));
}

// One GEMM layer: C[8][4] = A @ B (single fp16 product), depth-1 pipelined.
// cur holds this layer's first chunk on entry; on exit it holds the first
// chunk of the layer at next_rb (prefetched during this layer's last MMAs).
template <int KS>
static __device__ __forceinline__ void run_layer(uint32_t base_lane,
                                                 int row_rb, int next_rb,
                                                 const uint32_t off[4],
                                                 const uint32_t A[4][4],
                                                 float C[8][4], uint32_t cur[4]) {
#pragma unroll
    for (int j = 0; j < 8; j++)
#pragma unroll
        for (int q = 0; q < 4; q++) C[j][q] = 0.0f;

#pragma unroll
    for (int n = 0; n < KS * 4; n++) {
        const int s = n >> 2, jj = n & 3;
        const int n1 = n + 1;
        uint32_t a_next;
        if (n1 < KS * 4)
            a_next = base_lane + (uint32_t)(row_rb + (n1 >> 2) * 16) * 128 + off[n1 & 3];
        else
            a_next = base_lane + (uint32_t)next_rb * 128 + off[0];
        uint32_t nxt[4];
        ldsm4t(a_next, nxt);                      // in flight while MMAs run
        mma16816(C[2 * jj],     A[s], cur[0], cur[1]);
        mma16816(C[2 * jj + 1], A[s], cur[2], cur[3]);
        cur[0] = nxt[0]; cur[1] = nxt[1]; cur[2] = nxt[2]; cur[3] = nxt[3];
    }
}

// bias + relu + fp16 pack: C (this layer) -> A fragments (next layer)
static __device__ __forceinline__ void epi_relu_pack(const float* bias, int t4,
                                                     const float C[8][4], uint32_t A[4][4]) {
#pragma unroll
    for (int j = 0; j < 8; j++) {
        float b0 = bias[8 * j + 2 * t4];
        float b1 = bias[8 * j + 2 * t4 + 1];
        float v0 = fmaxf(C[j][0] + b0, 0.0f);
        float v1 = fmaxf(C[j][1] + b1, 0.0f);
        float v2 = fmaxf(C[j][2] + b0, 0.0f);
        float v3 = fmaxf(C[j][3] + b1, 0.0f);
        int s = j >> 1;
        int fi = (j & 1) * 2;
        A[s][fi]     = pack_f16(v0, v1);
        A[s][fi + 1] = pack_f16(v2, v3);
    }
}

// Gather layer-1 A fragments from the 8 live px float4 (even cols of x).
static __device__ __forceinline__ void frags_from_x(const float4 px[8], uint32_t A[4][4]) {
#pragma unroll
    for (int s = 0; s < 2; s++) {
        const float4& f0 = px[s * 4 + 0];   // row r0,   col-half u=0
        const float4& f1 = px[s * 4 + 1];   // row r0,   col-half u=1
        const float4& f2 = px[s * 4 + 2];   // row r0+8, u=0
        const float4& f3 = px[s * 4 + 3];   // row r0+8, u=1
        A[s][0] = pack_f16(f0.x, f0.z);
        A[s][1] = pack_f16(f2.x, f2.z);
        A[s][2] = pack_f16(f1.x, f1.z);
        A[s][3] = pack_f16(f3.x, f3.z);
    }
}

static __device__ __forceinline__ void load_px(const float* xb, int r0, int t4, float4 px[8]) {
#pragma unroll
    for (int s = 0; s < 2; s++) {
        const float4* p0 = (const float4*)(xb + r0 * 64 + s * 32) + t4;
        const float4* p1 = (const float4*)(xb + (r0 + 8) * 64 + s * 32) + t4;
        px[s * 4 + 0] = __ldg(p0);
        px[s * 4 + 1] = __ldg(p0 + 4);
        px[s * 4 + 2] = __ldg(p1);
        px[s * 4 + 3] = __ldg(p1 + 4);
    }
}

__global__ void __launch_bounds__(TPB, 2)
affine_coupling_hmma(const float* __restrict__ x,
                     const float* __restrict__ W1, const float* __restrict__ b1,
                     const float* __restrict__ W2, const float* __restrict__ b2,
                     const float* __restrict__ W3, const float* __restrict__ b3,
                     float* __restrict__ out, int nrows) {
    extern __shared__ char sm[];
    const uint32_t smb = smem_u32_of(sm);

    const int tid  = threadIdx.x;
    const int wid  = tid >> 5;
    const int lane = tid & 31;
    const int g    = lane >> 2;
    const int t4   = lane & 3;
    const int lane15 = lane & 15;
    const int lanehi = (lane >> 4) & 1;       // 0: chunk j0, 1: chunk j1
    const int r0 = wid * 16 + g;              // first owned row

    // ---- weight prep: fp16, SW128 swizzled [k][n] rows of 128B ----
    for (int e = tid; e < 10240; e += TPB) {
        const float* src; int rel, rb;
        if (e < 2048)      { src = W1; rel = e;        rb = 0;  }
        else if (e < 6144) { src = W2; rel = e - 2048; rb = 32; }
        else               { src = W3; rel = e - 6144; rb = 96; }
        int k = rel >> 6, n = rel & 63;
        float w = __ldg(src + rel);
        uint32_t off = SWZ((uint32_t)((rb + k) * 128 + n * 2));
        *(__half*)(sm + WH + off) = __float2half_rn(w);
    }
    float* bias = (float*)(sm + BIAS_O);
    if (tid < 64) {
        bias[tid]       = __ldg(b1 + tid);
        bias[64 + tid]  = __ldg(b2 + tid);
        bias[128 + tid] = __ldg(b3 + tid);
    }
    __syncthreads();    // only barrier in the kernel

    const int ntiles = nrows / ROWS_PER_CTA;
    float* outs = out + (size_t)nrows * 64;   // s block base

    // Per-thread constant addressing: x7 loop-invariant, 4 chunk offsets.
    const uint32_t base_lane = smb + WH + (uint32_t)lane15 * 128;
    const int x7 = lane15 & 7;
    uint32_t off[4];
#pragma unroll
    for (int jj = 0; jj < 4; jj++)
        off[jj] = ((uint32_t)((2 * jj + lanehi) ^ x7)) << 4;

    // Prime the pipeline: layer-1 first chunk.
    uint32_t cur[4];
    ldsm4t(base_lane + off[0], cur);

    for (int tile = blockIdx.x; tile < ntiles; tile += gridDim.x) {
        const float* xb = x + (size_t)tile * ROWS_PER_CTA * 64;

        float4 px[8];
        load_px(xb, r0, t4, px);

        uint32_t A[4][4];
        float C[8][4];

        frags_from_x(px, A);

        // ---- 3 GEMM layers (handoff prefetch across boundaries) ----
        run_layer<2>(base_lane, 0,  32, off, A, C, cur);
        epi_relu_pack(bias, t4, C, A);
        run_layer<4>(base_lane, 32, 96, off, A, C, cur);
        epi_relu_pack(bias + 64, t4, C, A);
        run_layer<4>(base_lane, 96, 0,  off, A, C, cur);   // exits holding L1 chunk

        // ---- register-direct epilogue: y AND s straight from px + C ----
        // px block (s,u): odd cols -> sigma = 16s+8u+2*t4 -> s in C[2s+u],
        // t in C[2s+u+4], same lane, rows r0 (frag 0,1) / r0+8 (frag 2,3).
        {
            const float* b3s = bias + 128;
            float4* oy = (float4*)out + (size_t)tile * (ROWS_PER_CTA * 16);
            float*  oss = outs + (size_t)tile * (ROWS_PER_CTA * 32);
#pragma unroll
            for (int s = 0; s < 2; s++) {
#pragma unroll
                for (int u = 0; u < 2; u++) {
                    int js = 2 * s + u, jt = js + 4;
                    int sig = 16 * s + 8 * u + 2 * t4;
                    float bs0 = b3s[sig], bs1 = b3s[sig + 1];
                    float bt0 = b3s[32 + sig], bt1 = b3s[32 + sig + 1];

                    float sa0 = tanh_fast(C[js][0] + bs0);
                    float sb0 = tanh_fast(C[js][1] + bs1);
                    float sa1 = tanh_fast(C[js][2] + bs0);
                    float sb1 = tanh_fast(C[js][3] + bs1);
                    float ta0 = C[jt][0] + bt0, tb0 = C[jt][1] + bt1;
                    float ta1 = C[jt][2] + bt0, tb1 = C[jt][3] + bt1;

                    // s straight to global (32B-aligned 32B chunks per warp)
                    *(float2*)(oss + (size_t)r0 * 32 + sig)       = make_float2(sa0, sb0);
                    *(float2*)(oss + (size_t)(r0 + 8) * 32 + sig) = make_float2(sa1, sb1);

                    // y straight from registers
                    float4 v0 = px[4 * s + u];          // row r0
                    float4 v1 = px[4 * s + 2 + u];      // row r0+8
                    v0.y = fmaf(v0.y, __expf(sa0), ta0);
                    v0.w = fmaf(v0.w, __expf(sb0), tb0);
                    v1.y = fmaf(v1.y, __expf(sa1), ta1);
                    v1.w = fmaf(v1.w, __expf(sb1), tb1);
                    int c4 = (32 * s + 16 * u) >> 2;    // float4 col index base
                    oy[r0 * 16 + c4 + t4]       = v0;
                    oy[(r0 + 8) * 16 + c4 + t4] = v1;
                }
            }
        }
        // no barrier: weights read-only, all outputs register-sourced
    }
}

extern "C" void kernel_launch(void* const* d_in, const int* in_sizes, int n_in,
                              void* d_out, int out_size) {
    const float* x  = (const float*)d_in[0];
    const float* W1 = (const float*)d_in[1];
    const float* b1 = (const float*)d_in[2];
    const float* W2 = (const float*)d_in[3];
    const float* b2 = (const float*)d_in[4];
    const float* W3 = (const float*)d_in[5];
    const float* b3 = (const float*)d_in[6];
    float* out = (float*)d_out;

    const int nrows = in_sizes[0] / 64;
    const int ntiles = nrows / ROWS_PER_CTA;
    int grid = 296;                      // 2 CTAs/SM * 148 SMs
    if (grid > ntiles) grid = ntiles;

    static int smem_set = 0;
    if (!smem_set) {
        cudaFuncSetAttribute(affine_coupling_hmma,
                             cudaFuncAttributeMaxDynamicSharedMemorySize, SMEM_BYTES);
        smem_set = 1;
    }
    affine_coupling_hmma<<<grid, TPB, SMEM_BYTES>>>(x, W1, b1, W2, b2, W3, b3, out, nrows);
}